// round 11
// baseline (speedup 1.0000x reference)
#include <cuda_runtime.h>
#include <cuda_fp16.h>
#include <cstdint>

#define NPTS 262144
#define CHN 96
#define KOFF 27
#define NCHUNK 81           // 27 offsets x 3 chunks of 32 K each
#define NTHREADS 256
#define NSTAGE 4
#define MTILE 256

// SMEM layout (dynamic):
#define SIDX_OFF 0          // int[27][256] = 27648 B
#define A_OFF    27648      // 4 bufs x 20480 B (256 rows x 80B stride, fp16)
#define W_OFF    (27648 + 4 * 20480)        // 4 bufs x 6656 B
#define SMEMTOT  (W_OFF + 4 * 6656)         // 136192 B

// ---------------- static device buffers (no allocs allowed) ----------------
__device__ __align__(16) __half g_fh[(size_t)NPTS * CHN];    // feats fp16
__device__ __align__(16) __half g_x1h[(size_t)NPTS * CHN];   // layer-1 out fp16
// W fp16, padded: [2 layers][81 chunks][32 k][104 n]; chunk = 3328 halfs
__device__ __align__(16) __half g_Wh[2 * NCHUNK * 32 * 104];

// ---------------- helpers ----------------
__device__ __forceinline__ uint32_t smem_u32(const void* p) {
    uint32_t a;
    asm("{ .reg .u64 t; cvta.to.shared.u64 t, %1; cvt.u32.u64 %0, t; }" : "=r"(a) : "l"(p));
    return a;
}
__device__ __forceinline__ void cpa16(uint32_t d, const void* s, int sz) {
    asm volatile("cp.async.cg.shared.global [%0], [%1], 16, %2;"
        :: "r"(d), "l"(__cvta_generic_to_global(s)), "r"(sz) : "memory");
}
__device__ __forceinline__ void ldm4(uint32_t* r, uint32_t addr) {
    asm volatile("ldmatrix.sync.aligned.m8n8.x4.shared.b16 {%0,%1,%2,%3}, [%4];"
        : "=r"(r[0]), "=r"(r[1]), "=r"(r[2]), "=r"(r[3]) : "r"(addr));
}
__device__ __forceinline__ void ldm4t(uint32_t* r, uint32_t addr) {
    asm volatile("ldmatrix.sync.aligned.m8n8.x4.trans.shared.b16 {%0,%1,%2,%3}, [%4];"
        : "=r"(r[0]), "=r"(r[1]), "=r"(r[2]), "=r"(r[3]) : "r"(addr));
}
__device__ __forceinline__ void mma16816(float* d, const uint32_t* a, uint32_t b0, uint32_t b1) {
    asm volatile("mma.sync.aligned.m16n8k16.row.col.f32.f16.f16.f32 "
        "{%0,%1,%2,%3},{%4,%5,%6,%7},{%8,%9},{%0,%1,%2,%3};"
        : "+f"(d[0]), "+f"(d[1]), "+f"(d[2]), "+f"(d[3])
        : "r"(a[0]), "r"(a[1]), "r"(a[2]), "r"(a[3]), "r"(b0), "r"(b1));
}

// ---------------- prep kernels ----------------
__global__ void split_kernel(const float* __restrict__ src, __half* __restrict__ dst, int n) {
    int i = blockIdx.x * blockDim.x + threadIdx.x;
    if (i < n) dst[i] = __float2half(src[i]);
}

__global__ void wprep_kernel(const float* __restrict__ W1, const float* __restrict__ W2) {
    int i = blockIdx.x * blockDim.x + threadIdx.x;   // over 2*81*32*104
    if (i >= 2 * NCHUNK * 32 * 104) return;
    int n = i % 104;
    int rest = i / 104;
    int kk = rest % 32;  rest /= 32;
    int c = rest % NCHUNK;
    int layer = rest / NCHUNK;
    float w = 0.f;
    if (n < CHN) {
        int k = c / 3, j = (c % 3) * 32 + kk;
        const float* W = layer ? W2 : W1;
        w = W[(size_t)k * CHN * CHN + (size_t)j * CHN + n];
    }
    g_Wh[i] = __float2half(w);
}

// ---------------- main gather-GEMM layer kernel (fp16 HMMA, M=256) ----------------
__global__ void __launch_bounds__(NTHREADS, 1)
sconv_hmma(const __half* __restrict__ fin,    // fp16 input [N, CH]
           const float* __restrict__ resid,   // fp32 residual or nullptr
           const int* __restrict__ nidx, const int* __restrict__ nmask,
           const __half* __restrict__ Wh,     // layer slice: [81][32][104]
           const float* __restrict__ bias, const float* __restrict__ alpha,
           void* __restrict__ outp, int out_half)
{
    extern __shared__ unsigned char smem[];
    const uint32_t sbase = smem_u32(smem);
    const int tid = threadIdx.x;
    const int wid = tid >> 5, l = tid & 31;
    const int base = blockIdx.x * MTILE;
    int* sIdx = (int*)(smem + SIDX_OFF);

    // preload idx with mask folded in
    for (int o = tid; o < KOFF * MTILE; o += NTHREADS) {
        const int k = o >> 8, t = o & 255;
        const int row = nidx[(size_t)k * NPTS + base + t];
        sIdx[o] = nmask[(size_t)k * NPTS + base + t] ? row : -1;
    }
    __syncthreads();

    const int mrow = (wid & 3) * 64;     // warp M offset (64 pts)
    const int ncol = (wid >> 2) * 48;    // warp N offset (48 ch)

    float acc[4][6][4];
    #pragma unroll
    for (int mt = 0; mt < 4; ++mt)
        #pragma unroll
        for (int nt = 0; nt < 6; ++nt)
            #pragma unroll
            for (int q = 0; q < 4; ++q) acc[mt][nt][q] = 0.f;

    // async prefetch of chunk c into stage buffer (1 thread per point row)
    auto prefetch = [&](int c) {
        const int buf = c & (NSTAGE - 1);
        const int k = c / 3, cpart = c % 3;
        const int gidx = sIdx[(k << 8) + tid];
        const __half* gsrc = fin + (size_t)(gidx < 0 ? 0 : gidx) * CHN + cpart * 32;
        const int sz = (gidx < 0) ? 0 : 16;
        const uint32_t sa = sbase + A_OFF + buf * 20480 + tid * 80;
        cpa16(sa,      gsrc,      sz);
        cpa16(sa + 16, gsrc + 8,  sz);
        cpa16(sa + 32, gsrc + 16, sz);
        cpa16(sa + 48, gsrc + 24, sz);
        // W copy: 6656 B contiguous = 416 uint4
        const uint4* ws = (const uint4*)(Wh + (size_t)c * 3328);
        const uint32_t wd = sbase + W_OFF + buf * 6656;
        cpa16(wd + tid * 16, ws + tid, 16);
        if (tid < 160) cpa16(wd + (tid + 256) * 16, ws + tid + 256, 16);
        asm volatile("cp.async.commit_group;" ::: "memory");
    };

    prefetch(0);
    prefetch(1);
    prefetch(2);

    // ldmatrix lane addressing
    const int arow_off = (l & 7) + ((l >> 3) & 1) * 8;
    const int acol_off = ((l >> 4) & 1) * 8;

    for (int c = 0; c < NCHUNK; ++c) {
        const int buf = c & (NSTAGE - 1);
        // chunk c complete when at most 2 newer groups are pending
        asm volatile("cp.async.wait_group 2;" ::: "memory");
        __syncthreads();   // data visible + all warps done with MMA(c-1) -> stage buf free
        if (c + 3 < NCHUNK) prefetch(c + 3);

        const uint32_t aB = sbase + A_OFF + buf * 20480;
        const uint32_t wB = sbase + W_OFF + buf * 6656;

        #pragma unroll
        for (int kh = 0; kh < 2; ++kh) {
            uint32_t a[4][4];
            #pragma unroll
            for (int mt = 0; mt < 4; ++mt) {
                const int r = mrow + mt * 16 + arow_off;
                ldm4(a[mt], aB + (uint32_t)(r * 80 + (kh * 16 + acol_off) * 2));
            }
            const int kr = kh * 16 + arow_off;
            #pragma unroll
            for (int np = 0; np < 3; ++np) {
                const int nc = ncol + np * 16 + acol_off;
                uint32_t b[4];
                ldm4t(b, wB + (uint32_t)(kr * 208 + nc * 2));
                #pragma unroll
                for (int hf = 0; hf < 2; ++hf) {
                    const int nt = np * 2 + hf;
                    #pragma unroll
                    for (int mt = 0; mt < 4; ++mt)
                        mma16816(acc[mt][nt], a[mt], b[2 * hf], b[2 * hf + 1]);
                }
            }
        }
    }

    // ---- epilogue: bias, optional residual, PReLU, store from mma accum regs ----
    const float a0 = alpha[0];
    float2 b2[6];
    #pragma unroll
    for (int nt = 0; nt < 6; ++nt) {
        const int col = ncol + nt * 8 + (l & 3) * 2;
        b2[nt] = make_float2(bias[col], bias[col + 1]);
    }
    #pragma unroll
    for (int mt = 0; mt < 4; ++mt) {
        #pragma unroll
        for (int half = 0; half < 2; ++half) {
            const size_t pt = (size_t)(base + mrow + mt * 16 + (l >> 2) + half * 8);
            #pragma unroll
            for (int nt = 0; nt < 6; ++nt) {
                const int col = ncol + nt * 8 + (l & 3) * 2;
                float v0 = acc[mt][nt][2 * half]     + b2[nt].x;
                float v1 = acc[mt][nt][2 * half + 1] + b2[nt].y;
                if (resid != nullptr) {
                    const float2 r = *(const float2*)(resid + pt * CHN + col);
                    v0 += r.x; v1 += r.y;
                }
                v0 = (v0 > 0.f) ? v0 : a0 * v0;
                v1 = (v1 > 0.f) ? v1 : a0 * v1;
                if (out_half) {
                    *(__half2*)((__half*)outp + pt * CHN + col) = __floats2half2_rn(v0, v1);
                } else {
                    *(float2*)((float*)outp + pt * CHN + col) = make_float2(v0, v1);
                }
            }
        }
    }
}

extern "C" void kernel_launch(void* const* d_in, const int* in_sizes, int n_in,
                              void* d_out, int out_size)
{
    const float* feats = (const float*)d_in[0];
    const int*   idx   = (const int*)d_in[1];
    const int*   mask  = (const int*)d_in[2];
    const float* W1    = (const float*)d_in[3];
    const float* b1    = (const float*)d_in[4];
    const float* a1    = (const float*)d_in[5];
    const float* W2    = (const float*)d_in[6];
    const float* b2    = (const float*)d_in[7];
    const float* a2    = (const float*)d_in[8];

    __half *fh, *x1h, *wh;
    cudaGetSymbolAddress((void**)&fh, g_fh);
    cudaGetSymbolAddress((void**)&x1h, g_x1h);
    cudaGetSymbolAddress((void**)&wh, g_Wh);

    static bool attr_done = false;
    if (!attr_done) {
        cudaFuncSetAttribute(sconv_hmma, cudaFuncAttributeMaxDynamicSharedMemorySize, SMEMTOT);
        attr_done = true;
    }

    const int nelem = NPTS * CHN;
    split_kernel<<<(nelem + 255) / 256, 256>>>(feats, fh, nelem);
    const int nw = 2 * NCHUNK * 32 * 104;
    wprep_kernel<<<(nw + 255) / 256, 256>>>(W1, W2);

    const size_t wstride = (size_t)NCHUNK * 3328;
    dim3 grid(NPTS / MTILE), block(NTHREADS);
    sconv_hmma<<<grid, block, SMEMTOT>>>(fh, nullptr, idx, mask,
                                         wh, b1, a1, (void*)x1h, 1);
    sconv_hmma<<<grid, block, SMEMTOT>>>(x1h, feats, idx, mask,
                                         wh + wstride, b2, a2, d_out, 0);
}

// round 13
// speedup vs baseline: 1.2593x; 1.2593x over previous
#include <cuda_runtime.h>
#include <cuda_fp16.h>
#include <cstdint>

#define NPTS 262144
#define CHN 96
#define KOFF 27
#define NCHUNK 81           // 27 offsets x 3 chunks of 32 K each
#define NTHREADS 256
#define NSTAGE 4

// SMEM layout (dynamic):
#define SIDX_OFF 0          // int[27][128] = 13824 B
#define A_OFF    13824      // 4 bufs x 10240 B (128 rows x 80B stride, fp16)
#define SMEMTOT  (13824 + 4 * 10240)   // 54784 B

// ---------------- static device buffers (no allocs allowed) ----------------
__device__ __align__(16) __half g_fh[(size_t)NPTS * CHN];    // feats fp16
__device__ __align__(16) __half g_x1h[(size_t)NPTS * CHN];   // layer-1 out fp16
// W in mma-B-fragment layout: [2 layers][81 c][2 g][2 kh][3 np][32 lane][4 b32]
#define WFRAG_PER_LAYER (NCHUNK * 2 * 2 * 3 * 32 * 4)
__device__ __align__(16) uint32_t g_Wf[2 * WFRAG_PER_LAYER];

// ---------------- helpers ----------------
__device__ __forceinline__ uint32_t smem_u32(const void* p) {
    uint32_t a;
    asm("{ .reg .u64 t; cvta.to.shared.u64 t, %1; cvt.u32.u64 %0, t; }" : "=r"(a) : "l"(p));
    return a;
}
__device__ __forceinline__ void cpa16(uint32_t d, const void* s, int sz) {
    asm volatile("cp.async.cg.shared.global [%0], [%1], 16, %2;"
        :: "r"(d), "l"(__cvta_generic_to_global(s)), "r"(sz) : "memory");
}
__device__ __forceinline__ void ldm4(uint32_t* r, uint32_t addr) {
    asm volatile("ldmatrix.sync.aligned.m8n8.x4.shared.b16 {%0,%1,%2,%3}, [%4];"
        : "=r"(r[0]), "=r"(r[1]), "=r"(r[2]), "=r"(r[3]) : "r"(addr));
}
__device__ __forceinline__ void mma16816(float* d, const uint32_t* a, uint32_t b0, uint32_t b1) {
    asm volatile("mma.sync.aligned.m16n8k16.row.col.f32.f16.f16.f32 "
        "{%0,%1,%2,%3},{%4,%5,%6,%7},{%8,%9},{%0,%1,%2,%3};"
        : "+f"(d[0]), "+f"(d[1]), "+f"(d[2]), "+f"(d[3])
        : "r"(a[0]), "r"(a[1]), "r"(a[2]), "r"(a[3]), "r"(b0), "r"(b1));
}

// ---------------- prep kernels ----------------
__global__ void split_kernel(const float* __restrict__ src, __half* __restrict__ dst, int n) {
    int i = blockIdx.x * blockDim.x + threadIdx.x;
    if (i < n) dst[i] = __float2half(src[i]);
}

// Build W fragments per the documented m16n8k16 B-operand register mapping:
//   reg(hf,ri) of lane l = half2( B[k0][n], B[k0+1][n] ),
//   k0 = kh*16 + (l%4)*2 + ri*8,  n = g*48 + np*16 + hf*8 + l/4
__global__ void wfrag_kernel(const float* __restrict__ W1, const float* __restrict__ W2) {
    int i = blockIdx.x * blockDim.x + threadIdx.x;   // over 2 * WFRAG_PER_LAYER
    if (i >= 2 * WFRAG_PER_LAYER) return;
    int r    = i & 3;
    int lane = (i >> 2) & 31;
    int rest = i >> 7;
    int np = rest % 3; rest /= 3;
    int kh = rest & 1; rest >>= 1;
    int g  = rest & 1; rest >>= 1;
    int c  = rest % NCHUNK;
    int layer = rest / NCHUNK;
    int hf = r >> 1, ri = r & 1;
    int n  = g * 48 + np * 16 + hf * 8 + (lane >> 2);
    int kk = kh * 16 + (lane & 3) * 2 + ri * 8;
    int koff = c / 3;
    int j  = (c % 3) * 32 + kk;
    const float* W = layer ? W2 : W1;
    const size_t wb = (size_t)koff * CHN * CHN + (size_t)j * CHN + n;
    __half lo = __float2half(W[wb]);
    __half hi = __float2half(W[wb + CHN]);
    g_Wf[i] = (uint32_t)__half_as_ushort(lo) | ((uint32_t)__half_as_ushort(hi) << 16);
}

// ---------------- main gather-GEMM layer kernel (fp16 HMMA, M=128) ----------------
__global__ void __launch_bounds__(NTHREADS, 2)
sconv_hmma(const __half* __restrict__ fin,    // fp16 input [N, CH]
           const float* __restrict__ resid,   // fp32 residual or nullptr
           const int* __restrict__ nidx, const int* __restrict__ nmask,
           const uint4* __restrict__ Wf,      // layer fragment slice
           const float* __restrict__ bias, const float* __restrict__ alpha,
           void* __restrict__ outp, int out_half)
{
    extern __shared__ unsigned char smem[];
    const uint32_t sbase = smem_u32(smem);
    const int tid = threadIdx.x;
    const int wid = tid >> 5, l = tid & 31;
    const int base = blockIdx.x * 128;
    int* sIdx = (int*)(smem + SIDX_OFF);

    // preload idx with mask folded in
    for (int o = tid; o < KOFF * 128; o += NTHREADS) {
        const int k = o >> 7, t = o & 127;
        const int row = nidx[(size_t)k * NPTS + base + t];
        sIdx[o] = nmask[(size_t)k * NPTS + base + t] ? row : -1;
    }
    __syncthreads();

    const int mrow = (wid & 3) * 32;     // warp M offset (32 pts)
    const int g    = wid >> 2;           // warp N group (48 ch each)
    const int ncol = g * 48;
    const int grow = tid >> 1, gh = tid & 1;   // gather: 2 thr/point, 16 halfs each

    float acc[2][6][4];
    #pragma unroll
    for (int mt = 0; mt < 2; ++mt)
        #pragma unroll
        for (int nt = 0; nt < 6; ++nt)
            #pragma unroll
            for (int q = 0; q < 4; ++q) acc[mt][nt][q] = 0.f;

    // async prefetch of chunk c's A tile into stage buffer
    auto prefetch = [&](int c) {
        const int buf = c & (NSTAGE - 1);
        const int k = c / 3, cpart = c % 3;
        const int gidx = sIdx[(k << 7) + grow];
        const __half* gsrc = fin + (size_t)(gidx < 0 ? 0 : gidx) * CHN + cpart * 32 + gh * 16;
        const int sz = (gidx < 0) ? 0 : 16;
        const uint32_t sa = sbase + A_OFF + buf * 10240 + grow * 80 + gh * 32;
        cpa16(sa, gsrc, sz);
        cpa16(sa + 16, gsrc + 8, sz);
        asm volatile("cp.async.commit_group;" ::: "memory");
    };

    prefetch(0);
    prefetch(1);
    prefetch(2);

    // ldmatrix lane addressing
    const int arow_off = (l & 7) + ((l >> 3) & 1) * 8;
    const int acol_off = ((l >> 4) & 1) * 8;

    for (int c = 0; c < NCHUNK; ++c) {
        const int buf = c & (NSTAGE - 1);
        asm volatile("cp.async.wait_group 2;" ::: "memory");
        __syncthreads();
        if (c + 3 < NCHUNK) prefetch(c + 3);

        const uint32_t aB = sbase + A_OFF + buf * 10240;

        // W fragments: 6 coalesced LDG.128 per warp, straight from L2-resident table
        const uint4* wf = Wf + ((size_t)(c * 2 + g) * 6) * 32 + l;
        uint4 wb[2][3];
        #pragma unroll
        for (int kh = 0; kh < 2; ++kh)
            #pragma unroll
            for (int np = 0; np < 3; ++np)
                wb[kh][np] = wf[(kh * 3 + np) * 32];

        #pragma unroll
        for (int kh = 0; kh < 2; ++kh) {
            uint32_t a[2][4];
            #pragma unroll
            for (int mt = 0; mt < 2; ++mt) {
                const int r = mrow + mt * 16 + arow_off;
                ldm4(a[mt], aB + (uint32_t)(r * 80 + (kh * 16 + acol_off) * 2));
            }
            #pragma unroll
            for (int np = 0; np < 3; ++np) {
                const uint4 b = wb[kh][np];
                #pragma unroll
                for (int mt = 0; mt < 2; ++mt) {
                    mma16816(acc[mt][np * 2 + 0], a[mt], b.x, b.y);   // hf = 0
                    mma16816(acc[mt][np * 2 + 1], a[mt], b.z, b.w);   // hf = 1
                }
            }
        }
    }

    // ---- epilogue: bias, optional residual, PReLU, store from mma accum regs ----
    const float a0 = alpha[0];
    float2 b2[6];
    #pragma unroll
    for (int nt = 0; nt < 6; ++nt) {
        const int col = ncol + nt * 8 + (l & 3) * 2;
        b2[nt] = make_float2(bias[col], bias[col + 1]);
    }
    #pragma unroll
    for (int mt = 0; mt < 2; ++mt) {
        #pragma unroll
        for (int half = 0; half < 2; ++half) {
            const size_t pt = (size_t)(base + mrow + mt * 16 + (l >> 2) + half * 8);
            #pragma unroll
            for (int nt = 0; nt < 6; ++nt) {
                const int col = ncol + nt * 8 + (l & 3) * 2;
                float v0 = acc[mt][nt][2 * half]     + b2[nt].x;
                float v1 = acc[mt][nt][2 * half + 1] + b2[nt].y;
                if (resid != nullptr) {
                    const float2 r = *(const float2*)(resid + pt * CHN + col);
                    v0 += r.x; v1 += r.y;
                }
                v0 = (v0 > 0.f) ? v0 : a0 * v0;
                v1 = (v1 > 0.f) ? v1 : a0 * v1;
                if (out_half) {
                    *(__half2*)((__half*)outp + pt * CHN + col) = __floats2half2_rn(v0, v1);
                } else {
                    *(float2*)((float*)outp + pt * CHN + col) = make_float2(v0, v1);
                }
            }
        }
    }
}

extern "C" void kernel_launch(void* const* d_in, const int* in_sizes, int n_in,
                              void* d_out, int out_size)
{
    const float* feats = (const float*)d_in[0];
    const int*   idx   = (const int*)d_in[1];
    const int*   mask  = (const int*)d_in[2];
    const float* W1    = (const float*)d_in[3];
    const float* b1    = (const float*)d_in[4];
    const float* a1    = (const float*)d_in[5];
    const float* W2    = (const float*)d_in[6];
    const float* b2    = (const float*)d_in[7];
    const float* a2    = (const float*)d_in[8];

    __half *fh, *x1h;
    uint32_t* wf;
    cudaGetSymbolAddress((void**)&fh, g_fh);
    cudaGetSymbolAddress((void**)&x1h, g_x1h);
    cudaGetSymbolAddress((void**)&wf, g_Wf);

    static bool attr_done = false;
    if (!attr_done) {
        cudaFuncSetAttribute(sconv_hmma, cudaFuncAttributeMaxDynamicSharedMemorySize, SMEMTOT);
        attr_done = true;
    }

    const int nelem = NPTS * CHN;
    split_kernel<<<(nelem + 255) / 256, 256>>>(feats, fh, nelem);
    const int nw = 2 * WFRAG_PER_LAYER;
    wfrag_kernel<<<(nw + 255) / 256, 256>>>(W1, W2);

    dim3 grid(NPTS / 128), block(NTHREADS);
    sconv_hmma<<<grid, block, SMEMTOT>>>(fh, nullptr, idx, mask,
                                         (const uint4*)wf, b1, a1, (void*)x1h, 1);
    sconv_hmma<<<grid, block, SMEMTOT>>>(x1h, feats, idx, mask,
                                         (const uint4*)(wf + WFRAG_PER_LAYER),
                                         b2, a2, d_out, 0);
}